// round 15
// baseline (speedup 1.0000x reference)
#include <cuda_runtime.h>
#include <cuda_fp16.h>
#include <cstdint>

// ============================================================================
// Soft-quantization codebook kernel — ldmatrix + mma.sync HMMA path.
//
// R14 -> R15 (scatter was latency-bound: 1 item/thread = no ILP; 5 launches):
//   * hist/scatter: 4 items per thread (float4 x load, 4 independent chains)
//   * both scan levels fused into ONE single-block kernel; binBase folded
//     into g_ofs so scatter does a single L2 load
//   * pipeline is now 4 launches: hist -> scan -> scatter -> main
// Main kernel identical to R14 (M=32 warp tiles, const sum column, WRAD=28).
// ============================================================================

#define ROWSMAX  262144
#define KANCH    256
#define EDIM     64
#define B_STRIDE 144                // bytes per B k-row (64 f16 + pad)
#define WRAD     28                 // window radius in anchors
#define NBLK     64                 // sort blocks (4096 items each)

__device__ int    g_cnt[KANCH * NBLK];
__device__ int    g_ofs[KANCH * NBLK];     // includes bin base after k_scan
__device__ float2 g_sorted[ROWSMAX];       // .x = x value, .y = idx bits

__device__ __forceinline__ uint32_t smem_u32(const void* p) {
    uint32_t a;
    asm("{ .reg .u64 t; cvta.to.shared.u64 t, %1; cvt.u32.u64 %0, t; }" : "=r"(a) : "l"(p));
    return a;
}

__device__ __forceinline__ float ex2f(float x) {
    float r;
    asm("ex2.approx.ftz.f32 %0, %1;" : "=f"(r) : "f"(x));
    return r;
}

__device__ __forceinline__ int anchor_bin(float xv, float A0, float rdlt) {
    int i0 = __float2int_rn((xv - A0) * rdlt);
    return min(max(i0, 0), KANCH - 1);
}

#define LDMATRIX_X4T(r0, r1, r2, r3, addr)                                        \
    asm volatile("ldmatrix.sync.aligned.m8n8.x4.trans.shared.b16 {%0,%1,%2,%3}, [%4];" \
        : "=r"(r0), "=r"(r1), "=r"(r2), "=r"(r3) : "r"(addr))

#define MMA16816(c, a, b0, b1)                                                    \
    asm volatile("mma.sync.aligned.m16n8k16.row.col.f32.f16.f16.f32 "             \
        "{%0,%1,%2,%3}, {%4,%5,%6,%7}, {%8,%9}, {%0,%1,%2,%3};"                   \
        : "+f"((c)[0]), "+f"((c)[1]), "+f"((c)[2]), "+f"((c)[3])                  \
        : "r"((a)[0]), "r"((a)[1]), "r"((a)[2]), "r"((a)[3]),                     \
          "r"(b0), "r"(b1))

#define CVT_F16X2(d, hi, lo) \
    asm("cvt.rn.f16x2.f32 %0, %1, %2;" : "=r"(d) : "f"(hi), "f"(lo))

// warp-aggregated smem histogram add: returns this lane's offset within bin
__device__ __forceinline__ int warp_agg_add(int* sh, int bin, int lane) {
    const unsigned mask = __match_any_sync(0xffffffffu, bin);
    const int leader   = __ffs(mask) - 1;
    const int lanerank = __popc(mask & ((1u << lane) - 1u));
    int base = 0;
    if (lane == leader) base = atomicAdd(&sh[bin], __popc(mask));
    base = __shfl_sync(0xffffffffu, base, leader);
    return base + lanerank;
}

// ---------------- sort pipeline: 3 kernels, ILP-4 ----------------

__global__ void __launch_bounds__(1024)
k_hist(const float* __restrict__ xg, const float* __restrict__ anchors_g) {
    __shared__ int sh[KANCH];
    const int tid = threadIdx.x;
    const int lane = tid & 31;
    if (tid < KANCH) sh[tid] = 0;
    __syncthreads();
    const float A0 = anchors_g[0];
    const float rdlt = 1.0f / (anchors_g[1] - anchors_g[0]);
    const float4 xv4 = reinterpret_cast<const float4*>(xg)[blockIdx.x * 1024 + tid];
    const float xs[4] = {xv4.x, xv4.y, xv4.z, xv4.w};
    #pragma unroll
    for (int j = 0; j < 4; j++) {
        const int bin = anchor_bin(xs[j], A0, rdlt);
        const unsigned mask = __match_any_sync(0xffffffffu, bin);
        if (lane == __ffs(mask) - 1) atomicAdd(&sh[bin], __popc(mask));
    }
    __syncthreads();
    if (tid < KANCH) g_cnt[tid * NBLK + blockIdx.x] = sh[tid];
}

// single block: both scan levels fused; writes g_ofs with bin base folded in
__global__ void __launch_bounds__(1024)
k_scan() {
    extern __shared__ int s[];
    int* sCnt  = s;                       // [KANCH*NBLK] = 16384
    int* sTot  = s + KANCH * NBLK;        // [KANCH]
    int* sBase = sTot + KANCH;            // [KANCH]
    const int tid  = threadIdx.x;
    const int lane = tid & 31;
    const int warp = tid >> 5;

    #pragma unroll
    for (int i = 0; i < KANCH * NBLK / 1024; i++)
        sCnt[tid + i * 1024] = g_cnt[tid + i * 1024];
    __syncthreads();

    // per-bin exclusive scan over NBLK=64 entries (2 per lane, warp shfl scan)
    #pragma unroll
    for (int r = 0; r < KANCH / 32; r++) {
        const int bin = r * 32 + warp;
        int* row = sCnt + bin * NBLK;
        const int a = row[lane * 2], b = row[lane * 2 + 1];
        const int pair = a + b;
        int incl = pair;
        #pragma unroll
        for (int off = 1; off < 32; off <<= 1) {
            const int u = __shfl_up_sync(0xffffffffu, incl, off);
            if (lane >= off) incl += u;
        }
        const int excl = incl - pair;
        row[lane * 2]     = excl;
        row[lane * 2 + 1] = excl + a;
        if (lane == 31) sTot[bin] = incl;
    }
    __syncthreads();

    // bin-level exclusive scan (Hillis-Steele, guarded)
    int v = (tid < KANCH) ? sTot[tid] : 0;
    int run = v;
    #pragma unroll
    for (int off = 1; off < KANCH; off <<= 1) {
        const int u = (tid >= off && tid < KANCH) ? sTot[tid - off] : 0;
        __syncthreads();
        if (tid < KANCH) sTot[tid] = run = run + u;
        __syncthreads();
    }
    if (tid < KANCH) sBase[tid] = run - v;
    __syncthreads();

    #pragma unroll
    for (int i = 0; i < KANCH * NBLK / 1024; i++) {
        const int idx = tid + i * 1024;
        g_ofs[idx] = sCnt[idx] + sBase[idx >> 6];    // idx>>6 = bin
    }
}

__global__ void __launch_bounds__(1024)
k_scatter(const float* __restrict__ xg, const float* __restrict__ anchors_g) {
    __shared__ int sh[KANCH];
    const int tid = threadIdx.x;
    const int lane = tid & 31;
    if (tid < KANCH) sh[tid] = 0;
    __syncthreads();
    const float A0 = anchors_g[0];
    const float rdlt = 1.0f / (anchors_g[1] - anchors_g[0]);
    const int iBase = (blockIdx.x * 1024 + tid) * 4;
    const float4 xv4 = reinterpret_cast<const float4*>(xg)[blockIdx.x * 1024 + tid];
    const float xs[4] = {xv4.x, xv4.y, xv4.z, xv4.w};
    #pragma unroll
    for (int j = 0; j < 4; j++) {
        const int bin = anchor_bin(xs[j], A0, rdlt);
        const int off = warp_agg_add(sh, bin, lane);
        const int pos = g_ofs[bin * NBLK + blockIdx.x] + off;
        g_sorted[pos] = make_float2(xs[j], __int_as_float(iBase + j));
    }
}

// ---------------- main kernel: M=32 warp tiles on globally sorted rows ----------------

__global__ void __launch_bounds__(128, 3)
softquant_kernel(const float* __restrict__ anchors_g,
                 const float* __restrict__ emb_g,
                 const float* __restrict__ gamma_g,
                 float* __restrict__ out_g,
                 int ntiles)                      // tiles of 128 rows
{
    __shared__ __align__(128) unsigned char sBmem[KANCH * B_STRIDE];  // 36864 B
    __shared__ float sAnch[KANCH];

    const uint32_t smB = smem_u32(sBmem);

    const int tid   = threadIdx.x;
    const int lane  = tid & 31;
    const int warp  = tid >> 5;
    const int group = lane >> 2;     // 0..7
    const int q     = lane & 3;      // k-slot quad index

    // ---- one-time per CTA: E f32 -> f16 smem B cols 0..63 ----
    #pragma unroll
    for (int i = 0; i < 32; i++) {
        const int idx4 = tid + i * 128;
        const float4 v = reinterpret_cast<const float4*>(emb_g)[idx4];
        const int base = idx4 * 4;
        const int k = base >> 6, n = base & 63;
        uint32_t h01, h23;
        CVT_F16X2(h01, v.y, v.x);
        CVT_F16X2(h23, v.w, v.z);
        asm volatile("st.shared.v2.b32 [%0], {%1, %2};"
                     :: "r"(smB + (uint32_t)(k * B_STRIDE + n * 2)), "r"(h01), "r"(h23));
    }
    sAnch[tid]       = anchors_g[tid];
    sAnch[tid + 128] = anchors_g[tid + 128];
    __syncthreads();

    // ---- per-thread constants ----
    const float g    = fabsf(gamma_g[0]);
    const float l2e  = 1.4426950408889634f;
    const float c1   = -g * l2e;
    const float A0   = sAnch[0];
    const float dlt  = sAnch[1] - sAnch[0];
    const float rdlt = 1.0f / dlt;
    const float gd2l = g * dlt * dlt * l2e;
    const float m1   = 32.0f * g * dlt * l2e;
    const float m2   = -256.0f * gd2l;
    const float U1   = ex2f(-32.0f * gd2l);
    const float U8   = ex2f(-256.0f * gd2l);
    const float U9   = U8 * U1;
    const float Q    = ex2f(-512.0f * gd2l);

    // sum-column B fragment: col 64 = 1.0 for every k -> constant regs
    const uint32_t bSum = (group == 0) ? 0x3C003C00u : 0u;

    const uint32_t bLane = smB + (uint32_t)(lane & 15) * B_STRIDE + (uint32_t)(lane >> 4) * 16u;

    for (int tile = blockIdx.x; tile < ntiles; tile += gridDim.x) {
        const int rBase = tile * 128 + warp * 32 + group;

        // ---- per-row setup + hoisted recurrence init (4 rows/thread) ----
        float xv[4], wi[4][4], w[4][4], T[4];
        int   s0r[4], rowOf[4];
        int   lo = 16, hi = 0;
        #pragma unroll
        for (int j = 0; j < 4; j++) {
            const int rk = rBase + ((j >> 1) << 4) + ((j & 1) << 3);
            const float2 sv = g_sorted[rk];       // one 8B load
            xv[j]    = sv.x;
            rowOf[j] = __float_as_int(sv.y);
            const int i0 = anchor_bin(xv[j], A0, rdlt);
            s0r[j] = max(i0 - WRAD, 0) >> 4;
            const int se = (min(i0 + WRAD, KANCH - 1) >> 4) + 1;
            lo = min(lo, s0r[j]);
            hi = max(hi, se);

            const int kb0 = s0r[j] * 16 + q * 2;
            const float2 aA = *reinterpret_cast<const float2*>(sAnch + kb0);
            const float2 aB = *reinterpret_cast<const float2*>(sAnch + kb0 + 8);
            const float d0 = xv[j] - aA.x, d1 = xv[j] - aA.y;
            const float d8 = xv[j] - aB.x, d9 = xv[j] - aB.y;
            wi[j][0] = ex2f((c1 * d0) * d0);
            wi[j][1] = ex2f((c1 * d1) * d1);
            wi[j][2] = ex2f((c1 * d8) * d8);
            wi[j][3] = ex2f((c1 * d9) * d9);
            T[j]     = ex2f(m1 * d0 + m2);
            w[j][0] = 0.0f; w[j][1] = 0.0f; w[j][2] = 0.0f; w[j][3] = 0.0f;
        }
        // warp union of step ranges (globally sorted rows -> very tight)
        #pragma unroll
        for (int off = 16; off > 0; off >>= 1) {
            lo = min(lo, __shfl_xor_sync(0xffffffffu, lo, off));
            hi = max(hi, __shfl_xor_sync(0xffffffffu, hi, off));
        }

        float acc[2][9][4];
        #pragma unroll
        for (int mt = 0; mt < 2; mt++)
            #pragma unroll
            for (int nt = 0; nt < 9; nt++)
                #pragma unroll
                for (int c = 0; c < 4; c++) acc[mt][nt][c] = 0.0f;

        for (int s = lo; s < hi; s++) {
            // ---- B fragments: 8 E-octets (shared by both row halves) ----
            const uint32_t bRow = bLane + (uint32_t)(16 * s) * B_STRIDE;
            uint32_t b[8][2];
            #pragma unroll
            for (int nt = 0; nt < 8; nt += 2)
                LDMATRIX_X4T(b[nt][0], b[nt][1], b[nt + 1][0], b[nt + 1][1],
                             bRow + (uint32_t)(nt * 16));

            // ---- weights: branch-free recurrence (FSEL inject) ----
            #pragma unroll
            for (int j = 0; j < 4; j++) {
                const bool isInit  = (s == s0r[j]);
                const bool isAfter = (s > s0r[j]);
                const float f  = T[j];
                const float w0 = w[j][0] * f;
                const float w1 = w[j][1] * (f * U1);
                const float w2 = w[j][2] * (f * U8);
                const float w3 = w[j][3] * (f * U9);
                w[j][0] = isInit ? wi[j][0] : w0;
                w[j][1] = isInit ? wi[j][1] : w1;
                w[j][2] = isInit ? wi[j][2] : w2;
                w[j][3] = isInit ? wi[j][3] : w3;
                T[j]    = isAfter ? f * Q : f;
            }

            // ---- pack A fragments ----
            uint32_t afr[2][4];
            #pragma unroll
            for (int mt = 0; mt < 2; mt++) {
                const int j0 = mt * 2, j1 = mt * 2 + 1;
                CVT_F16X2(afr[mt][0], w[j0][1], w[j0][0]);
                CVT_F16X2(afr[mt][1], w[j1][1], w[j1][0]);
                CVT_F16X2(afr[mt][2], w[j0][3], w[j0][2]);
                CVT_F16X2(afr[mt][3], w[j1][3], w[j1][2]);
            }

            #pragma unroll
            for (int nt = 0; nt < 8; nt++) {
                MMA16816(acc[0][nt], afr[0], b[nt][0], b[nt][1]);
                MMA16816(acc[1][nt], afr[1], b[nt][0], b[nt][1]);
            }
            MMA16816(acc[0][8], afr[0], bSum, bSum);
            MMA16816(acc[1][8], afr[1], bSum, bSum);
        }

        // ---- row inverse-sums from sum column (col 64: q==0, c0/c2) ----
        const int srcLane = lane & ~3;
        float iv[4];
        iv[0] = __shfl_sync(0xffffffffu, 1.0f / acc[0][8][0], srcLane);  // row group
        iv[1] = __shfl_sync(0xffffffffu, 1.0f / acc[0][8][2], srcLane);  // +8
        iv[2] = __shfl_sync(0xffffffffu, 1.0f / acc[1][8][0], srcLane);  // +16
        iv[3] = __shfl_sync(0xffffffffu, 1.0f / acc[1][8][2], srcLane);  // +24

        // ---- epilogue: write through the global row permutation ----
        #pragma unroll
        for (int mt = 0; mt < 2; mt++) {
            const float iv0 = iv[mt * 2 + 0];
            const float iv1 = iv[mt * 2 + 1];
            float* oLo = out_g + (size_t)rowOf[mt * 2 + 0] * EDIM + q * 2;
            float* oHi = out_g + (size_t)rowOf[mt * 2 + 1] * EDIM + q * 2;
            #pragma unroll
            for (int nt = 0; nt < 8; nt++) {
                float2 v0, v1;
                v0.x = acc[mt][nt][0] * iv0;  v0.y = acc[mt][nt][1] * iv0;
                v1.x = acc[mt][nt][2] * iv1;  v1.y = acc[mt][nt][3] * iv1;
                *reinterpret_cast<float2*>(oLo + nt * 8) = v0;
                *reinterpret_cast<float2*>(oHi + nt * 8) = v1;
            }
        }
    }
}

extern "C" void kernel_launch(void* const* d_in, const int* in_sizes, int n_in,
                              void* d_out, int out_size) {
    const float* x       = (const float*)d_in[0];
    const float* anchors = (const float*)d_in[1];
    const float* emb     = (const float*)d_in[2];
    const float* gamma   = (const float*)d_in[3];
    float* out = (float*)d_out;

    const int rows   = in_sizes[0];          // 262144
    const int ntiles = rows / 128;           // 2048 tiles of 128 rows

    int dev = 0, nsm = 148;
    cudaGetDevice(&dev);
    cudaDeviceGetAttribute(&nsm, cudaDevAttrMultiProcessorCount, dev);
    int grid = 3 * nsm;                      // persistent: 3 CTAs per SM
    if (grid > ntiles) grid = ntiles;

    const int scanSmem = (KANCH * NBLK + 2 * KANCH) * (int)sizeof(int);  // ~67.5 KB
    cudaFuncSetAttribute(k_scan, cudaFuncAttributeMaxDynamicSharedMemorySize, scanSmem);

    k_hist<<<NBLK, 1024>>>(x, anchors);
    k_scan<<<1, 1024, scanSmem>>>();
    k_scatter<<<NBLK, 1024>>>(x, anchors);
    softquant_kernel<<<grid, 128>>>(anchors, emb, gamma, out, ntiles);
}

// round 16
// speedup vs baseline: 1.4494x; 1.4494x over previous
#include <cuda_runtime.h>
#include <cuda_fp16.h>
#include <cstdint>

// ============================================================================
// Soft-quantization codebook kernel — ldmatrix + mma.sync HMMA path.
//
// R15 -> R16: global pre-sort abandoned (3 rounds of evidence: its pipeline
// costs ~17us regardless of structure; R10's in-CTA sort was nearly free).
// Single kernel = R10 structure (per-tile counting sort, M=32 warp tiles,
// FSEL recurrence) + proven deltas since:
//   * const sum column (col64 B fragment = register constant; 9th ldmatrix
//     and its smem init deleted)
//   * WRAD 40 -> 20 (dropped tail mass ~1.7e-5 relative, << f16 noise)
//   * warp-aggregated atomics in the per-tile sort histogram
// ============================================================================

#define MTILE    128
#define KANCH    256
#define EDIM     64
#define B_STRIDE 144                // bytes per B k-row (64 f16 + pad)
#define WRAD     20                 // window radius in anchors

__device__ __forceinline__ uint32_t smem_u32(const void* p) {
    uint32_t a;
    asm("{ .reg .u64 t; cvta.to.shared.u64 t, %1; cvt.u32.u64 %0, t; }" : "=r"(a) : "l"(p));
    return a;
}

__device__ __forceinline__ float ex2f(float x) {
    float r;
    asm("ex2.approx.ftz.f32 %0, %1;" : "=f"(r) : "f"(x));
    return r;
}

#define LDMATRIX_X4T(r0, r1, r2, r3, addr)                                        \
    asm volatile("ldmatrix.sync.aligned.m8n8.x4.trans.shared.b16 {%0,%1,%2,%3}, [%4];" \
        : "=r"(r0), "=r"(r1), "=r"(r2), "=r"(r3) : "r"(addr))

#define MMA16816(c, a, b0, b1)                                                    \
    asm volatile("mma.sync.aligned.m16n8k16.row.col.f32.f16.f16.f32 "             \
        "{%0,%1,%2,%3}, {%4,%5,%6,%7}, {%8,%9}, {%0,%1,%2,%3};"                   \
        : "+f"((c)[0]), "+f"((c)[1]), "+f"((c)[2]), "+f"((c)[3])                  \
        : "r"((a)[0]), "r"((a)[1]), "r"((a)[2]), "r"((a)[3]),                     \
          "r"(b0), "r"(b1))

#define CVT_F16X2(d, hi, lo) \
    asm("cvt.rn.f16x2.f32 %0, %1, %2;" : "=r"(d) : "f"(hi), "f"(lo))

__global__ void __launch_bounds__(128, 3)
softquant_kernel(const float* __restrict__ xg,
                 const float* __restrict__ anchors_g,
                 const float* __restrict__ emb_g,
                 const float* __restrict__ gamma_g,
                 float* __restrict__ out_g,
                 int ntiles)
{
    __shared__ __align__(128) unsigned char sBmem[KANCH * B_STRIDE];  // 36864 B
    __shared__ float sAnch[KANCH];
    __shared__ int   sHist[KANCH];      // sort histogram / prefix
    __shared__ float sXs[MTILE];        // sorted x values
    __shared__ int   sRow[MTILE];       // sorted rank -> original row
    __shared__ int   sWS[4];            // per-warp scan totals

    const uint32_t smB = smem_u32(sBmem);

    const int tid   = threadIdx.x;
    const int lane  = tid & 31;
    const int warp  = tid >> 5;
    const int R0    = warp * 32;
    const int group = lane >> 2;     // 0..7
    const int q     = lane & 3;      // k-slot quad index

    // ---- one-time per CTA: E f32 -> f16 smem B cols 0..63 ----
    #pragma unroll
    for (int i = 0; i < 32; i++) {
        const int idx4 = tid + i * 128;
        const float4 v = reinterpret_cast<const float4*>(emb_g)[idx4];
        const int base = idx4 * 4;
        const int k = base >> 6, n = base & 63;
        uint32_t h01, h23;
        CVT_F16X2(h01, v.y, v.x);
        CVT_F16X2(h23, v.w, v.z);
        asm volatile("st.shared.v2.b32 [%0], {%1, %2};"
                     :: "r"(smB + (uint32_t)(k * B_STRIDE + n * 2)), "r"(h01), "r"(h23));
    }
    sAnch[tid]       = anchors_g[tid];
    sAnch[tid + 128] = anchors_g[tid + 128];
    __syncthreads();

    // ---- per-thread constants ----
    const float g    = fabsf(gamma_g[0]);
    const float l2e  = 1.4426950408889634f;
    const float c1   = -g * l2e;
    const float A0   = sAnch[0];
    const float dlt  = sAnch[1] - sAnch[0];
    const float rdlt = 1.0f / dlt;
    const float gd2l = g * dlt * dlt * l2e;
    const float m1   = 32.0f * g * dlt * l2e;
    const float m2   = -256.0f * gd2l;
    const float U1   = ex2f(-32.0f * gd2l);
    const float U8   = ex2f(-256.0f * gd2l);
    const float U9   = U8 * U1;
    const float Q    = ex2f(-512.0f * gd2l);

    // sum-column B fragment: col 64 = 1.0 for every k -> constant regs
    const uint32_t bSum = (group == 0) ? 0x3C003C00u : 0u;

    const uint32_t bLane = smB + (uint32_t)(lane & 15) * B_STRIDE + (uint32_t)(lane >> 4) * 16u;

    for (int tile = blockIdx.x; tile < ntiles; tile += gridDim.x) {
        // ================= per-tile counting sort of 128 rows by anchor bin =================
        sHist[tid] = 0;
        sHist[tid + 128] = 0;
        __syncthreads();
        const float xv0 = xg[(size_t)tile * MTILE + tid];
        int i0t = __float2int_rn((xv0 - A0) * rdlt);
        i0t = min(max(i0t, 0), KANCH - 1);
        // warp-aggregated histogram add
        int localOff;
        {
            const unsigned mask = __match_any_sync(0xffffffffu, i0t);
            const int leader    = __ffs(mask) - 1;
            const int lanerank  = __popc(mask & ((1u << lane) - 1u));
            int base = 0;
            if (lane == leader) base = atomicAdd(&sHist[i0t], __popc(mask));
            localOff = __shfl_sync(0xffffffffu, base, leader) + lanerank;
        }
        __syncthreads();
        {   // exclusive prefix scan over 256 bins (2 bins/thread + warp shfl scan)
            const int a = sHist[2 * tid], b = sHist[2 * tid + 1];
            const int sv = a + b;
            int incl = sv;
            #pragma unroll
            for (int off = 1; off < 32; off <<= 1) {
                const int n = __shfl_up_sync(0xffffffffu, incl, off);
                if (lane >= off) incl += n;
            }
            if (lane == 31) sWS[warp] = incl;
            __syncthreads();
            int wbase = 0;
            #pragma unroll
            for (int wj = 0; wj < 4; wj++) wbase += (wj < warp) ? sWS[wj] : 0;
            const int exclA = wbase + incl - sv;
            sHist[2 * tid]     = exclA;
            sHist[2 * tid + 1] = exclA + a;
        }
        __syncthreads();
        const int rank = sHist[i0t] + localOff;
        sXs[rank]  = xv0;
        sRow[rank] = tid;
        __syncthreads();

        // ---- per-row setup + hoisted recurrence init (rows = sorted ranks) ----
        float xv[4], wi[4][4], w[4][4], T[4];
        int   s0r[4], rowOf[4];
        int   lo = 16, hi = 0;
        #pragma unroll
        for (int j = 0; j < 4; j++) {
            const int rk = R0 + ((j >> 1) << 4) + ((j & 1) << 3) + group;
            xv[j]    = sXs[rk];
            rowOf[j] = sRow[rk];
            int i0 = __float2int_rn((xv[j] - A0) * rdlt);
            i0 = min(max(i0, 0), KANCH - 1);
            s0r[j] = max(i0 - WRAD, 0) >> 4;
            const int se = (min(i0 + WRAD, KANCH - 1) >> 4) + 1;
            lo = min(lo, s0r[j]);
            hi = max(hi, se);

            const int kb0 = s0r[j] * 16 + q * 2;
            const float2 aA = *reinterpret_cast<const float2*>(sAnch + kb0);
            const float2 aB = *reinterpret_cast<const float2*>(sAnch + kb0 + 8);
            const float d0 = xv[j] - aA.x, d1 = xv[j] - aA.y;
            const float d8 = xv[j] - aB.x, d9 = xv[j] - aB.y;
            wi[j][0] = ex2f((c1 * d0) * d0);
            wi[j][1] = ex2f((c1 * d1) * d1);
            wi[j][2] = ex2f((c1 * d8) * d8);
            wi[j][3] = ex2f((c1 * d9) * d9);
            T[j]     = ex2f(m1 * d0 + m2);
            w[j][0] = 0.0f; w[j][1] = 0.0f; w[j][2] = 0.0f; w[j][3] = 0.0f;
        }
        // warp union of step ranges (tile-sorted rows -> tight union)
        #pragma unroll
        for (int off = 16; off > 0; off >>= 1) {
            lo = min(lo, __shfl_xor_sync(0xffffffffu, lo, off));
            hi = max(hi, __shfl_xor_sync(0xffffffffu, hi, off));
        }

        float acc[2][9][4];
        #pragma unroll
        for (int mt = 0; mt < 2; mt++)
            #pragma unroll
            for (int nt = 0; nt < 9; nt++)
                #pragma unroll
                for (int c = 0; c < 4; c++) acc[mt][nt][c] = 0.0f;

        for (int s = lo; s < hi; s++) {
            // ---- B fragments: 8 E-octets (shared by both row halves) ----
            const uint32_t bRow = bLane + (uint32_t)(16 * s) * B_STRIDE;
            uint32_t b[8][2];
            #pragma unroll
            for (int nt = 0; nt < 8; nt += 2)
                LDMATRIX_X4T(b[nt][0], b[nt][1], b[nt + 1][0], b[nt + 1][1],
                             bRow + (uint32_t)(nt * 16));

            // ---- weights: branch-free recurrence (FSEL inject) ----
            #pragma unroll
            for (int j = 0; j < 4; j++) {
                const bool isInit  = (s == s0r[j]);
                const bool isAfter = (s > s0r[j]);
                const float f  = T[j];
                const float w0 = w[j][0] * f;
                const float w1 = w[j][1] * (f * U1);
                const float w2 = w[j][2] * (f * U8);
                const float w3 = w[j][3] * (f * U9);
                w[j][0] = isInit ? wi[j][0] : w0;
                w[j][1] = isInit ? wi[j][1] : w1;
                w[j][2] = isInit ? wi[j][2] : w2;
                w[j][3] = isInit ? wi[j][3] : w3;
                T[j]    = isAfter ? f * Q : f;
            }

            // ---- pack A fragments ----
            uint32_t afr[2][4];
            #pragma unroll
            for (int mt = 0; mt < 2; mt++) {
                const int j0 = mt * 2, j1 = mt * 2 + 1;
                CVT_F16X2(afr[mt][0], w[j0][1], w[j0][0]);
                CVT_F16X2(afr[mt][1], w[j1][1], w[j1][0]);
                CVT_F16X2(afr[mt][2], w[j0][3], w[j0][2]);
                CVT_F16X2(afr[mt][3], w[j1][3], w[j1][2]);
            }

            #pragma unroll
            for (int nt = 0; nt < 8; nt++) {
                MMA16816(acc[0][nt], afr[0], b[nt][0], b[nt][1]);
                MMA16816(acc[1][nt], afr[1], b[nt][0], b[nt][1]);
            }
            MMA16816(acc[0][8], afr[0], bSum, bSum);
            MMA16816(acc[1][8], afr[1], bSum, bSum);
        }

        // ---- row inverse-sums from sum column (col 64: q==0, c0/c2) ----
        const int srcLane = lane & ~3;
        float iv[4];
        iv[0] = __shfl_sync(0xffffffffu, 1.0f / acc[0][8][0], srcLane);  // rank R0+group
        iv[1] = __shfl_sync(0xffffffffu, 1.0f / acc[0][8][2], srcLane);  // +8
        iv[2] = __shfl_sync(0xffffffffu, 1.0f / acc[1][8][0], srcLane);  // +16
        iv[3] = __shfl_sync(0xffffffffu, 1.0f / acc[1][8][2], srcLane);  // +24

        // ---- epilogue: write through the row permutation ----
        const size_t outTile = (size_t)tile * MTILE;
        #pragma unroll
        for (int mt = 0; mt < 2; mt++) {
            const float iv0 = iv[mt * 2 + 0];
            const float iv1 = iv[mt * 2 + 1];
            float* oLo = out_g + (outTile + rowOf[mt * 2 + 0]) * EDIM + q * 2;
            float* oHi = out_g + (outTile + rowOf[mt * 2 + 1]) * EDIM + q * 2;
            #pragma unroll
            for (int nt = 0; nt < 8; nt++) {
                float2 v0, v1;
                v0.x = acc[mt][nt][0] * iv0;  v0.y = acc[mt][nt][1] * iv0;
                v1.x = acc[mt][nt][2] * iv1;  v1.y = acc[mt][nt][3] * iv1;
                *reinterpret_cast<float2*>(oLo + nt * 8) = v0;
                *reinterpret_cast<float2*>(oHi + nt * 8) = v1;
            }
        }
        // next tile's sort phase begins with __syncthreads-protected writes.
    }
}

extern "C" void kernel_launch(void* const* d_in, const int* in_sizes, int n_in,
                              void* d_out, int out_size) {
    const float* x       = (const float*)d_in[0];
    const float* anchors = (const float*)d_in[1];
    const float* emb     = (const float*)d_in[2];
    const float* gamma   = (const float*)d_in[3];
    float* out = (float*)d_out;

    const int rows   = in_sizes[0];          // 262144
    const int ntiles = rows / MTILE;         // 2048

    int dev = 0, nsm = 148;
    cudaGetDevice(&dev);
    cudaDeviceGetAttribute(&nsm, cudaDevAttrMultiProcessorCount, dev);
    int grid = 3 * nsm;                      // persistent: 3 CTAs per SM
    if (grid > ntiles) grid = ntiles;

    softquant_kernel<<<grid, MTILE>>>(x, anchors, emb, gamma, out, ntiles);
}

// round 17
// speedup vs baseline: 1.5952x; 1.1006x over previous
#include <cuda_runtime.h>
#include <cuda_fp16.h>
#include <cstdint>

// ============================================================================
// Soft-quantization codebook kernel — ldmatrix + mma.sync HMMA path.
//
// R16 -> R17 (latency: per-tile sort barriers + cold x-load + wide unions):
//   * POOLED per-CTA sort: each persistent CTA sorts ALL its 4-6 tiles' rows
//     at once (one histogram/scan/scatter, 5 syncthreads total), then runs
//     the mainloop over 128-row slices of the pooled sorted order
//   * x loaded upfront with MLP-5 (independent LDGs)
//   * 32-of-~590 sorted ranks -> warp unions ~4.75 -> ~3.9 steps
// Mainloop itself identical to R16 (FSEL recurrence, const sum col, WRAD=20).
// ============================================================================

#define MTILE    128
#define KANCH    256
#define EDIM     64
#define B_STRIDE 144                // bytes per B k-row (64 f16 + pad)
#define WRAD     20                 // window radius in anchors
#define MAXT     6                  // max tiles per CTA

__device__ __forceinline__ uint32_t smem_u32(const void* p) {
    uint32_t a;
    asm("{ .reg .u64 t; cvta.to.shared.u64 t, %1; cvt.u32.u64 %0, t; }" : "=r"(a) : "l"(p));
    return a;
}

__device__ __forceinline__ float ex2f(float x) {
    float r;
    asm("ex2.approx.ftz.f32 %0, %1;" : "=f"(r) : "f"(x));
    return r;
}

#define LDMATRIX_X4T(r0, r1, r2, r3, addr)                                        \
    asm volatile("ldmatrix.sync.aligned.m8n8.x4.trans.shared.b16 {%0,%1,%2,%3}, [%4];" \
        : "=r"(r0), "=r"(r1), "=r"(r2), "=r"(r3) : "r"(addr))

#define MMA16816(c, a, b0, b1)                                                    \
    asm volatile("mma.sync.aligned.m16n8k16.row.col.f32.f16.f16.f32 "             \
        "{%0,%1,%2,%3}, {%4,%5,%6,%7}, {%8,%9}, {%0,%1,%2,%3};"                   \
        : "+f"((c)[0]), "+f"((c)[1]), "+f"((c)[2]), "+f"((c)[3])                  \
        : "r"((a)[0]), "r"((a)[1]), "r"((a)[2]), "r"((a)[3]),                     \
          "r"(b0), "r"(b1))

#define CVT_F16X2(d, hi, lo) \
    asm("cvt.rn.f16x2.f32 %0, %1, %2;" : "=r"(d) : "f"(hi), "f"(lo))

__global__ void __launch_bounds__(128, 3)
softquant_kernel(const float* __restrict__ xg,
                 const float* __restrict__ anchors_g,
                 const float* __restrict__ emb_g,
                 const float* __restrict__ gamma_g,
                 float* __restrict__ out_g,
                 int ntiles)
{
    __shared__ __align__(128) unsigned char sBmem[KANCH * B_STRIDE];  // 36864 B
    __shared__ float sAnch[KANCH];
    __shared__ int   sHist[KANCH];          // pooled sort histogram / prefix
    __shared__ float sXs[MAXT * MTILE];     // pooled sorted x values
    __shared__ int   sRow[MAXT * MTILE];    // pooled sorted rank -> absolute row
    __shared__ int   sWS[4];                // per-warp scan totals

    const uint32_t smB = smem_u32(sBmem);

    const int tid   = threadIdx.x;
    const int lane  = tid & 31;
    const int warp  = tid >> 5;
    const int R0    = warp * 32;
    const int group = lane >> 2;     // 0..7
    const int q     = lane & 3;      // k-slot quad index

    // ---- one-time per CTA: E f32 -> f16 smem B cols 0..63 ----
    #pragma unroll
    for (int i = 0; i < 32; i++) {
        const int idx4 = tid + i * 128;
        const float4 v = reinterpret_cast<const float4*>(emb_g)[idx4];
        const int base = idx4 * 4;
        const int k = base >> 6, n = base & 63;
        uint32_t h01, h23;
        CVT_F16X2(h01, v.y, v.x);
        CVT_F16X2(h23, v.w, v.z);
        asm volatile("st.shared.v2.b32 [%0], {%1, %2};"
                     :: "r"(smB + (uint32_t)(k * B_STRIDE + n * 2)), "r"(h01), "r"(h23));
    }
    sAnch[tid]       = anchors_g[tid];
    sAnch[tid + 128] = anchors_g[tid + 128];
    sHist[tid] = 0;
    sHist[tid + 128] = 0;
    __syncthreads();

    // ---- per-thread constants ----
    const float g    = fabsf(gamma_g[0]);
    const float l2e  = 1.4426950408889634f;
    const float c1   = -g * l2e;
    const float A0   = sAnch[0];
    const float dlt  = sAnch[1] - sAnch[0];
    const float rdlt = 1.0f / dlt;
    const float gd2l = g * dlt * dlt * l2e;
    const float m1   = 32.0f * g * dlt * l2e;
    const float m2   = -256.0f * gd2l;
    const float U1   = ex2f(-32.0f * gd2l);
    const float U8   = ex2f(-256.0f * gd2l);
    const float U9   = U8 * U1;
    const float Q    = ex2f(-512.0f * gd2l);

    // sum-column B fragment: col 64 = 1.0 for every k -> constant regs
    const uint32_t bSum = (group == 0) ? 0x3C003C00u : 0u;

    const uint32_t bLane = smB + (uint32_t)(lane & 15) * B_STRIDE + (uint32_t)(lane >> 4) * 16u;

    // ================= pooled sort: ALL of this CTA's tiles at once =================
    int nt = 0;
    int tiles[MAXT];
    #pragma unroll
    for (int i = 0; i < MAXT; i++) {
        const int t = blockIdx.x + i * gridDim.x;
        tiles[i] = t;
        if (t < ntiles) nt = i + 1;
    }

    // upfront x loads: MAXT independent LDGs (MLP hides DRAM latency)
    float xr[MAXT];
    #pragma unroll
    for (int i = 0; i < MAXT; i++)
        if (i < nt) xr[i] = xg[(size_t)tiles[i] * MTILE + tid];

    // warp-aggregated histogram over the pooled rows (nt is CTA-uniform)
    int bins[MAXT], lofs[MAXT];
    #pragma unroll
    for (int i = 0; i < MAXT; i++) {
        if (i < nt) {
            int b = __float2int_rn((xr[i] - A0) * rdlt);
            b = min(max(b, 0), KANCH - 1);
            bins[i] = b;
            const unsigned mask = __match_any_sync(0xffffffffu, b);
            const int leader    = __ffs(mask) - 1;
            const int lanerank  = __popc(mask & ((1u << lane) - 1u));
            int base = 0;
            if (lane == leader) base = atomicAdd(&sHist[b], __popc(mask));
            lofs[i] = __shfl_sync(0xffffffffu, base, leader) + lanerank;
        }
    }
    __syncthreads();
    {   // exclusive prefix scan over 256 bins (2 bins/thread + warp shfl scan)
        const int a = sHist[2 * tid], b = sHist[2 * tid + 1];
        const int sv = a + b;
        int incl = sv;
        #pragma unroll
        for (int off = 1; off < 32; off <<= 1) {
            const int n = __shfl_up_sync(0xffffffffu, incl, off);
            if (lane >= off) incl += n;
        }
        if (lane == 31) sWS[warp] = incl;
        __syncthreads();
        int wbase = 0;
        #pragma unroll
        for (int wj = 0; wj < 4; wj++) wbase += (wj < warp) ? sWS[wj] : 0;
        const int exclA = wbase + incl - sv;
        sHist[2 * tid]     = exclA;
        sHist[2 * tid + 1] = exclA + a;
    }
    __syncthreads();
    #pragma unroll
    for (int i = 0; i < MAXT; i++) {
        if (i < nt) {
            const int r = sHist[bins[i]] + lofs[i];
            sXs[r]  = xr[i];
            sRow[r] = tiles[i] * MTILE + tid;     // absolute row index
        }
    }
    __syncthreads();

    // ================= mainloop passes over 128-row slices of pooled order =================
    for (int p = 0; p < nt; p++) {
        const int rkBase = p * MTILE + R0 + group;

        // ---- per-row setup + hoisted recurrence init (4 rows/thread) ----
        float xv[4], wi[4][4], w[4][4], T[4];
        int   s0r[4], rowOf[4];
        int   lo = 16, hi = 0;
        #pragma unroll
        for (int j = 0; j < 4; j++) {
            const int rk = rkBase + ((j >> 1) << 4) + ((j & 1) << 3);
            xv[j]    = sXs[rk];
            rowOf[j] = sRow[rk];
            int i0 = __float2int_rn((xv[j] - A0) * rdlt);
            i0 = min(max(i0, 0), KANCH - 1);
            s0r[j] = max(i0 - WRAD, 0) >> 4;
            const int se = (min(i0 + WRAD, KANCH - 1) >> 4) + 1;
            lo = min(lo, s0r[j]);
            hi = max(hi, se);

            const int kb0 = s0r[j] * 16 + q * 2;
            const float2 aA = *reinterpret_cast<const float2*>(sAnch + kb0);
            const float2 aB = *reinterpret_cast<const float2*>(sAnch + kb0 + 8);
            const float d0 = xv[j] - aA.x, d1 = xv[j] - aA.y;
            const float d8 = xv[j] - aB.x, d9 = xv[j] - aB.y;
            wi[j][0] = ex2f((c1 * d0) * d0);
            wi[j][1] = ex2f((c1 * d1) * d1);
            wi[j][2] = ex2f((c1 * d8) * d8);
            wi[j][3] = ex2f((c1 * d9) * d9);
            T[j]     = ex2f(m1 * d0 + m2);
            w[j][0] = 0.0f; w[j][1] = 0.0f; w[j][2] = 0.0f; w[j][3] = 0.0f;
        }
        // warp union of step ranges (pool-sorted rows -> very tight)
        #pragma unroll
        for (int off = 16; off > 0; off >>= 1) {
            lo = min(lo, __shfl_xor_sync(0xffffffffu, lo, off));
            hi = max(hi, __shfl_xor_sync(0xffffffffu, hi, off));
        }

        float acc[2][9][4];
        #pragma unroll
        for (int mt = 0; mt < 2; mt++)
            #pragma unroll
            for (int ntt = 0; ntt < 9; ntt++)
                #pragma unroll
                for (int c = 0; c < 4; c++) acc[mt][ntt][c] = 0.0f;

        for (int s = lo; s < hi; s++) {
            // ---- B fragments: 8 E-octets (shared by both row halves) ----
            const uint32_t bRow = bLane + (uint32_t)(16 * s) * B_STRIDE;
            uint32_t b[8][2];
            #pragma unroll
            for (int ntt = 0; ntt < 8; ntt += 2)
                LDMATRIX_X4T(b[ntt][0], b[ntt][1], b[ntt + 1][0], b[ntt + 1][1],
                             bRow + (uint32_t)(ntt * 16));

            // ---- weights: branch-free recurrence (FSEL inject) ----
            #pragma unroll
            for (int j = 0; j < 4; j++) {
                const bool isInit  = (s == s0r[j]);
                const bool isAfter = (s > s0r[j]);
                const float f  = T[j];
                const float w0 = w[j][0] * f;
                const float w1 = w[j][1] * (f * U1);
                const float w2 = w[j][2] * (f * U8);
                const float w3 = w[j][3] * (f * U9);
                w[j][0] = isInit ? wi[j][0] : w0;
                w[j][1] = isInit ? wi[j][1] : w1;
                w[j][2] = isInit ? wi[j][2] : w2;
                w[j][3] = isInit ? wi[j][3] : w3;
                T[j]    = isAfter ? f * Q : f;
            }

            // ---- pack A fragments ----
            uint32_t afr[2][4];
            #pragma unroll
            for (int mt = 0; mt < 2; mt++) {
                const int j0 = mt * 2, j1 = mt * 2 + 1;
                CVT_F16X2(afr[mt][0], w[j0][1], w[j0][0]);
                CVT_F16X2(afr[mt][1], w[j1][1], w[j1][0]);
                CVT_F16X2(afr[mt][2], w[j0][3], w[j0][2]);
                CVT_F16X2(afr[mt][3], w[j1][3], w[j1][2]);
            }

            #pragma unroll
            for (int ntt = 0; ntt < 8; ntt++) {
                MMA16816(acc[0][ntt], afr[0], b[ntt][0], b[ntt][1]);
                MMA16816(acc[1][ntt], afr[1], b[ntt][0], b[ntt][1]);
            }
            MMA16816(acc[0][8], afr[0], bSum, bSum);
            MMA16816(acc[1][8], afr[1], bSum, bSum);
        }

        // ---- row inverse-sums from sum column (col 64: q==0, c0/c2) ----
        const int srcLane = lane & ~3;
        float iv[4];
        iv[0] = __shfl_sync(0xffffffffu, 1.0f / acc[0][8][0], srcLane);
        iv[1] = __shfl_sync(0xffffffffu, 1.0f / acc[0][8][2], srcLane);
        iv[2] = __shfl_sync(0xffffffffu, 1.0f / acc[1][8][0], srcLane);
        iv[3] = __shfl_sync(0xffffffffu, 1.0f / acc[1][8][2], srcLane);

        // ---- epilogue: write through the pooled row permutation (absolute rows) ----
        #pragma unroll
        for (int mt = 0; mt < 2; mt++) {
            const float iv0 = iv[mt * 2 + 0];
            const float iv1 = iv[mt * 2 + 1];
            float* oLo = out_g + (size_t)rowOf[mt * 2 + 0] * EDIM + q * 2;
            float* oHi = out_g + (size_t)rowOf[mt * 2 + 1] * EDIM + q * 2;
            #pragma unroll
            for (int ntt = 0; ntt < 8; ntt++) {
                float2 v0, v1;
                v0.x = acc[mt][ntt][0] * iv0;  v0.y = acc[mt][ntt][1] * iv0;
                v1.x = acc[mt][ntt][2] * iv1;  v1.y = acc[mt][ntt][3] * iv1;
                *reinterpret_cast<float2*>(oLo + ntt * 8) = v0;
                *reinterpret_cast<float2*>(oHi + ntt * 8) = v1;
            }
        }
    }
}

extern "C" void kernel_launch(void* const* d_in, const int* in_sizes, int n_in,
                              void* d_out, int out_size) {
    const float* x       = (const float*)d_in[0];
    const float* anchors = (const float*)d_in[1];
    const float* emb     = (const float*)d_in[2];
    const float* gamma   = (const float*)d_in[3];
    float* out = (float*)d_out;

    const int rows   = in_sizes[0];          // 262144
    const int ntiles = rows / MTILE;         // 2048

    int dev = 0, nsm = 148;
    cudaGetDevice(&dev);
    cudaDeviceGetAttribute(&nsm, cudaDevAttrMultiProcessorCount, dev);
    int grid = 3 * nsm;                      // persistent: 3 CTAs per SM
    if (grid > ntiles) grid = ntiles;
    // ensure every CTA's tile count fits MAXT
    const int minGrid = (ntiles + MAXT - 1) / MAXT;
    if (grid < minGrid) grid = minGrid;

    softquant_kernel<<<grid, MTILE>>>(x, anchors, emb, gamma, out, ntiles);
}